// round 8
// baseline (speedup 1.0000x reference)
#include <cuda_runtime.h>
#include <cstdint>

// Problem constants
#define BD    8
#define TD    4096
#define DD    512
#define DIE   1024          // DI
#define NROWS (BD*TD)       // 32768
#define LN_EPS 1e-5f

// ---------------- scratch (no cudaMalloc allowed) ----------------
__device__ float g_xz[(size_t)NROWS * 2 * DIE];
__device__ float g_cf[(size_t)NROWS * DIE];
__device__ float g_cb[(size_t)NROWS * DIE];
__device__ float g_pf[(size_t)NROWS * DIE];
__device__ float g_pb[(size_t)NROWS * DIE];
__device__ float g_y [(size_t)NROWS * DIE];
__device__ float g_o [(size_t)NROWS * DD];
__device__ float g_xr[(size_t)NROWS * DD];          // tf32-rounded x
__device__ float g_w1[(size_t)2 * DIE * DD];        // rounded in_proj_w
__device__ float g_wf[(size_t)DIE * DIE];           // rounded proj_fwd_w
__device__ float g_wb[(size_t)DIE * DIE];           // rounded proj_bwd_w
__device__ float g_wo[(size_t)DD * DIE];            // rounded out_proj_w

__device__ __forceinline__ float silu_f(float v) {
    return v / (1.f + __expf(-v));
}

__device__ __forceinline__ float tf32r(float f) {
    uint32_t u;
    asm("cvt.rna.tf32.f32 %0, %1;" : "=r"(u) : "f"(f));
    return __uint_as_float(u);
}

__device__ __forceinline__ uint32_t smem_to_u32(const void* p) {
    uint32_t a;
    asm("{ .reg .u64 t; cvta.to.shared.u64 t, %1; cvt.u32.u64 %0, t; }" : "=r"(a) : "l"(p));
    return a;
}

__device__ __forceinline__ void mma_tf32(float* c, const uint32_t* a,
                                         uint32_t b0, uint32_t b1) {
    asm volatile(
        "mma.sync.aligned.m16n8k8.row.col.f32.tf32.tf32.f32 "
        "{%0,%1,%2,%3}, {%4,%5,%6,%7}, {%8,%9}, {%0,%1,%2,%3};"
        : "+f"(c[0]), "+f"(c[1]), "+f"(c[2]), "+f"(c[3])
        : "r"(a[0]), "r"(a[1]), "r"(a[2]), "r"(a[3]), "r"(b0), "r"(b1));
}

__device__ __forceinline__ void ldsm4(uint32_t* r, uint32_t addr) {
    asm volatile("ldmatrix.sync.aligned.m8n8.x4.shared.b16 {%0,%1,%2,%3}, [%4];"
        : "=r"(r[0]), "=r"(r[1]), "=r"(r[2]), "=r"(r[3]) : "r"(addr));
}

#define CP16(dst, src) \
    asm volatile("cp.async.cg.shared.global [%0], [%1], 16;" :: "r"(dst), "l"(src))
#define CP_COMMIT() asm volatile("cp.async.commit_group;" ::: "memory")
#define CP_WAIT1()  asm volatile("cp.async.wait_group 1;" ::: "memory")

// =============== tf32 GEMM: C[M,N] = A[M,K] * B[N,K]^T (inputs pre-rounded) ===
// 128x256x32 CTA tile, 256 threads, 8 warps (2M x 4N), warp tile 64x64.
// 3-stage cp.async pipeline (stage = A 16KB + B 32KB = 48KB), fragments via
// ldmatrix.x4 (b16 mover on tf32 data).
// EPI==0: C = acc            EPI==1: C = silu(acc + bias[n])
#define ST_STRIDE 49152u
template<int EPI>
__global__ void __launch_bounds__(256, 1)
gemm_tc(const float* __restrict__ A, const float* __restrict__ B,
        const float* __restrict__ bias, float* __restrict__ C,
        int M, int N, int K)
{
    extern __shared__ char smem[];
    const uint32_t al = smem_to_u32(smem);

    const int tid = threadIdx.x;
    const int wid = tid >> 5, l = tid & 31;
    const int wm = wid >> 2, wn = wid & 3;

    const size_t row0 = (size_t)blockIdx.y * 128;
    const size_t col0 = (size_t)blockIdx.x * 256;

    // ---- cp.async invariants: thread -> (row = tid>>3 + 32i, kgroup = tid&7)
    const int ldr = tid >> 3;        // 0..31
    const int ldkg = tid & 7;
    const uint32_t sg = (uint32_t)(ldkg ^ (ldr & 7)) << 4;   // swizzled 16B group
    const float* gA = A + (row0 + ldr) * (size_t)K + ldkg * 4;
    const float* gB = B + (col0 + ldr) * (size_t)K + ldkg * 4;
    const uint32_t sA0 = al + ldr * 128 + sg;
    const uint32_t sB0 = al + 16384 + ldr * 128 + sg;

    // ---- fragment address invariants
    const uint32_t lr = l & 7, g01 = (l >> 3) & 1, g2 = (uint32_t)l >> 4;
    uint32_t aRow[4], bRow[4];
#pragma unroll
    for (int mi = 0; mi < 4; mi++)
        aRow[mi] = al + (uint32_t)(wm * 64 + mi * 16 + g01 * 8 + lr) * 128;
#pragma unroll
    for (int p = 0; p < 4; p++)
        bRow[p] = al + 16384 + (uint32_t)(wn * 64 + p * 16 + g2 * 8 + lr) * 128;

    float acc[4][8][4];
#pragma unroll
    for (int mi = 0; mi < 4; mi++)
#pragma unroll
        for (int j = 0; j < 8; j++)
#pragma unroll
            for (int t = 0; t < 4; t++) acc[mi][j][t] = 0.f;

    const int NC = K >> 5;

    // ---- prologue: load chunks 0,1 into stages 0,1
#pragma unroll
    for (int s = 0; s < 2; s++) {
        const float* pa = gA + s * 32;
        const float* pb = gB + s * 32;
        uint32_t da = sA0 + s * ST_STRIDE;
        uint32_t db = sB0 + s * ST_STRIDE;
#pragma unroll
        for (int i = 0; i < 4; i++)
            CP16(da + i * 4096, pa + (size_t)i * 32 * K);
#pragma unroll
        for (int i = 0; i < 8; i++)
            CP16(db + i * 4096, pb + (size_t)i * 32 * K);
        CP_COMMIT();
    }

    for (int c = 0; c < NC; ++c) {
        CP_WAIT1();
        __syncthreads();
        if (c + 2 < NC) {
            const int st = (c + 2) % 3;
            const float* pa = gA + (size_t)(c + 2) * 32;
            const float* pb = gB + (size_t)(c + 2) * 32;
            uint32_t da = sA0 + st * ST_STRIDE;
            uint32_t db = sB0 + st * ST_STRIDE;
#pragma unroll
            for (int i = 0; i < 4; i++)
                CP16(da + i * 4096, pa + (size_t)i * 32 * K);
#pragma unroll
            for (int i = 0; i < 8; i++)
                CP16(db + i * 4096, pb + (size_t)i * 32 * K);
        }
        CP_COMMIT();

        const uint32_t stOff = (uint32_t)(c % 3) * ST_STRIDE;
#pragma unroll
        for (int s = 0; s < 4; s++) {
            const uint32_t aOff = stOff + ((((uint32_t)(2 * s) + g2) ^ lr) << 4);
            const uint32_t bOff = stOff + ((((uint32_t)(2 * s) + g01) ^ lr) << 4);
            uint32_t af[4][4], bf[4][4];
#pragma unroll
            for (int mi = 0; mi < 4; mi++) ldsm4(af[mi], aRow[mi] + aOff);
#pragma unroll
            for (int p = 0; p < 4; p++)  ldsm4(bf[p], bRow[p] + bOff);
#pragma unroll
            for (int mi = 0; mi < 4; mi++)
#pragma unroll
                for (int p = 0; p < 4; p++) {
                    mma_tf32(acc[mi][2 * p],     af[mi], bf[p][0], bf[p][1]);
                    mma_tf32(acc[mi][2 * p + 1], af[mi], bf[p][2], bf[p][3]);
                }
        }
    }

    // ---- epilogue: acc[mi][nj] -> rows row0+wm*64+mi*16+{l>>2, +8},
    //      cols col0+wn*64+nj*8+(l&3)*2+{0,1}
    const int gq = l >> 2, qq = l & 3;
#pragma unroll
    for (int mi = 0; mi < 4; mi++) {
        size_t r1 = row0 + wm * 64 + mi * 16 + gq;
#pragma unroll
        for (int nj = 0; nj < 8; nj++) {
            size_t cc = col0 + wn * 64 + nj * 8 + qq * 2;
            float v00 = acc[mi][nj][0], v01 = acc[mi][nj][1];
            float v10 = acc[mi][nj][2], v11 = acc[mi][nj][3];
            if (EPI == 1) {
                float2 bb = *(const float2*)(bias + cc);
                v00 = silu_f(v00 + bb.x); v01 = silu_f(v01 + bb.y);
                v10 = silu_f(v10 + bb.x); v11 = silu_f(v11 + bb.y);
            }
            *(float2*)(C + r1 * N + cc)       = make_float2(v00, v01);
            *(float2*)(C + (r1 + 8) * N + cc) = make_float2(v10, v11);
        }
    }
}

// ---------------- tf32 pre-round (float4 grid-stride) -------------------------
__global__ void round_tf32(const float* __restrict__ src, float* __restrict__ dst,
                           long long n4)
{
    long long i = (long long)blockIdx.x * blockDim.x + threadIdx.x;
    if (i < n4) {
        float4 v = ((const float4*)src)[i];
        v.x = tf32r(v.x); v.y = tf32r(v.y); v.z = tf32r(v.z); v.w = tf32r(v.w);
        ((float4*)dst)[i] = v;
    }
}

// ---------------- fused depthwise causal (fwd) + anti-causal (bwd) conv ----------
// outputs rounded to tf32 (they feed the proj GEMMs)
__global__ void conv_dw(const float* __restrict__ xz,
                        const float* __restrict__ wf, const float* __restrict__ bf,
                        const float* __restrict__ wb, const float* __restrict__ bb,
                        float* __restrict__ cf, float* __restrict__ cb)
{
    long long id = (long long)blockIdx.x * blockDim.x + threadIdx.x;
    int c = (int)(id & (DIE - 1));
    long long m = id >> 10;
    int t = (int)(m & (TD - 1));
    long long base = m * (2 * DIE) + c;

    float accf = bf[c];
    float accb = bb[c];
#pragma unroll
    for (int k = 0; k < 7; k++) {
        float w = wf[c * 7 + k];
        float v = (t - 6 + k >= 0) ? xz[base + (long long)(k - 6) * (2 * DIE)] : 0.f;
        accf = fmaf(v, w, accf);
    }
#pragma unroll
    for (int j = 0; j < 7; j++) {
        float w = wb[c * 7 + (6 - j)];
        float v = (t + 1 + j < TD) ? xz[base + (long long)(j + 1) * (2 * DIE)] : 0.f;
        accb = fmaf(v, w, accb);
    }
    cf[id] = tf32r(accf);
    cb[id] = tf32r(accb);
}

// ---------------- combine: shifts + diag + gate (output rounded) ---------------
__global__ void combine_k(const float* __restrict__ xz,
                          const float* __restrict__ pf, const float* __restrict__ pb,
                          const float* __restrict__ diag, const float* __restrict__ gate,
                          float* __restrict__ y)
{
    long long id = (long long)blockIdx.x * blockDim.x + threadIdx.x;
    int e = (int)(id & (DIE - 1));
    long long m = id >> 10;
    int t = (int)(m & (TD - 1));

    float yf = (t > 0)      ? pf[id - DIE] : 0.f;
    float yb = (t < TD - 1) ? pb[id]       : 0.f;
    float xp = xz[m * (2 * DIE) + e];
    float z  = xz[m * (2 * DIE) + DIE + e];
    y[id] = tf32r((yf + yb + xp * diag[e]) * silu_f(z) * gate[0]);
}

// ---------------- residual + LayerNorm(512) -----------------------------------
__device__ __forceinline__ float warp_sum(float v) {
#pragma unroll
    for (int o = 16; o > 0; o >>= 1) v += __shfl_down_sync(0xffffffffu, v, o);
    return v;
}

__global__ void ln_kernel(const float* __restrict__ x, const float* __restrict__ o,
                          const float* __restrict__ g, const float* __restrict__ b,
                          float* __restrict__ out)
{
    const int m = blockIdx.x;
    const int tid = threadIdx.x;
    const size_t base = (size_t)m * DD;

    float4 xv = ((const float4*)(x + base))[tid];
    float4 ov = ((const float4*)(o + base))[tid];
    float4 h = make_float4(xv.x + ov.x, xv.y + ov.y, xv.z + ov.z, xv.w + ov.w);

    float s  = h.x + h.y + h.z + h.w;
    float ss = h.x * h.x + h.y * h.y + h.z * h.z + h.w * h.w;

    __shared__ float sh[4], sh2[4];
    float ws  = warp_sum(s);
    float wss = warp_sum(ss);
    if ((tid & 31) == 0) { sh[tid >> 5] = ws; sh2[tid >> 5] = wss; }
    __syncthreads();
    if (tid < 32) {
        float a  = (tid < 4) ? sh[tid]  : 0.f;
        float a2 = (tid < 4) ? sh2[tid] : 0.f;
        a  = warp_sum(a);
        a2 = warp_sum(a2);
        if (tid == 0) { sh[0] = a; sh2[0] = a2; }
    }
    __syncthreads();

    float mu  = sh[0] * (1.f / DD);
    float var = sh2[0] * (1.f / DD) - mu * mu;
    float inv = rsqrtf(var + LN_EPS);

    float4 gv = ((const float4*)g)[tid];
    float4 bv = ((const float4*)b)[tid];
    float4 r;
    r.x = (h.x - mu) * inv * gv.x + bv.x;
    r.y = (h.y - mu) * inv * gv.y + bv.y;
    r.z = (h.z - mu) * inv * gv.z + bv.z;
    r.w = (h.w - mu) * inv * gv.w + bv.w;
    ((float4*)(out + base))[tid] = r;
}

// ---------------- launch ------------------------------------------------------
#define GEMM_SMEM (3 * 49152)   // 144 KB

extern "C" void kernel_launch(void* const* d_in, const int* in_sizes, int n_in,
                              void* d_out, int out_size)
{
    const float* x          = (const float*)d_in[0];
    const float* in_proj_w  = (const float*)d_in[1];
    const float* conv_fwd_w = (const float*)d_in[2];
    const float* conv_fwd_b = (const float*)d_in[3];
    const float* proj_fwd_w = (const float*)d_in[4];
    const float* proj_fwd_b = (const float*)d_in[5];
    const float* conv_bwd_w = (const float*)d_in[6];
    const float* conv_bwd_b = (const float*)d_in[7];
    const float* proj_bwd_w = (const float*)d_in[8];
    const float* proj_bwd_b = (const float*)d_in[9];
    const float* diag       = (const float*)d_in[10];
    const float* gate       = (const float*)d_in[11];
    const float* out_proj_w = (const float*)d_in[12];
    const float* ln_g       = (const float*)d_in[13];
    const float* ln_b       = (const float*)d_in[14];

    float *xz, *cf, *cb, *pf, *pb, *y, *o, *xr, *w1, *wf, *wb, *wo;
    cudaGetSymbolAddress((void**)&xz, g_xz);
    cudaGetSymbolAddress((void**)&cf, g_cf);
    cudaGetSymbolAddress((void**)&cb, g_cb);
    cudaGetSymbolAddress((void**)&pf, g_pf);
    cudaGetSymbolAddress((void**)&pb, g_pb);
    cudaGetSymbolAddress((void**)&y,  g_y);
    cudaGetSymbolAddress((void**)&o,  g_o);
    cudaGetSymbolAddress((void**)&xr, g_xr);
    cudaGetSymbolAddress((void**)&w1, g_w1);
    cudaGetSymbolAddress((void**)&wf, g_wf);
    cudaGetSymbolAddress((void**)&wb, g_wb);
    cudaGetSymbolAddress((void**)&wo, g_wo);

    cudaFuncSetAttribute(gemm_tc<0>, cudaFuncAttributeMaxDynamicSharedMemorySize, GEMM_SMEM);
    cudaFuncSetAttribute(gemm_tc<1>, cudaFuncAttributeMaxDynamicSharedMemorySize, GEMM_SMEM);

    // 0) tf32 pre-rounding of all GEMM inputs not produced by our own kernels
    {
        long long n4;
        n4 = (long long)NROWS * DD / 4;
        round_tf32<<<(unsigned)((n4 + 255) / 256), 256>>>(x, xr, n4);
        n4 = (long long)2 * DIE * DD / 4;
        round_tf32<<<(unsigned)((n4 + 255) / 256), 256>>>(in_proj_w, w1, n4);
        n4 = (long long)DIE * DIE / 4;
        round_tf32<<<(unsigned)((n4 + 255) / 256), 256>>>(proj_fwd_w, wf, n4);
        round_tf32<<<(unsigned)((n4 + 255) / 256), 256>>>(proj_bwd_w, wb, n4);
        n4 = (long long)DD * DIE / 4;
        round_tf32<<<(unsigned)((n4 + 255) / 256), 256>>>(out_proj_w, wo, n4);
    }

    // 1) xz = xr @ w1^T          (32768 x 2048, K=512)
    gemm_tc<0><<<dim3(2048 / 256, NROWS / 128), 256, GEMM_SMEM>>>(
        xr, w1, nullptr, xz, NROWS, 2048, DD);
    // 2) both depthwise convs (outputs tf32-rounded)
    conv_dw<<<(NROWS * DIE) / 256, 256>>>(xz, conv_fwd_w, conv_fwd_b,
                                          conv_bwd_w, conv_bwd_b, cf, cb);
    // 3) pf = silu(cf @ wf^T + b)
    gemm_tc<1><<<dim3(DIE / 256, NROWS / 128), 256, GEMM_SMEM>>>(
        cf, wf, proj_fwd_b, pf, NROWS, DIE, DIE);
    // 4) pb = silu(cb @ wb^T + b)
    gemm_tc<1><<<dim3(DIE / 256, NROWS / 128), 256, GEMM_SMEM>>>(
        cb, wb, proj_bwd_b, pb, NROWS, DIE, DIE);
    // 5) y = (shift(pf) + mask(pb) + x_proj*diag) * silu(z) * gate  (rounded)
    combine_k<<<(NROWS * DIE) / 256, 256>>>(xz, pf, pb, diag, gate, y);
    // 6) o = y @ wo^T             (32768 x 512, K=1024)
    gemm_tc<0><<<dim3(DD / 256, NROWS / 128), 256, GEMM_SMEM>>>(
        y, wo, nullptr, o, NROWS, DD, DIE);
    // 7) out = LayerNorm(x + o)
    ln_kernel<<<NROWS, 128>>>(x, o, ln_g, ln_b, (float*)d_out);
}

// round 9
// speedup vs baseline: 1.4911x; 1.4911x over previous
#include <cuda_runtime.h>
#include <cuda_fp16.h>
#include <cstdint>

// Problem constants
#define BD    8
#define TD    4096
#define DD    512
#define DIE   1024          // DI
#define NROWS (BD*TD)       // 32768
#define LN_EPS 1e-5f

// ---------------- scratch (no cudaMalloc allowed) ----------------
__device__ __half g_xzh[(size_t)NROWS * 2 * DIE];   // gemm1 out (fp16)
__device__ __half g_cfh[(size_t)NROWS * DIE];
__device__ __half g_cbh[(size_t)NROWS * DIE];
__device__ __half g_pfh[(size_t)NROWS * DIE];
__device__ __half g_pbh[(size_t)NROWS * DIE];
__device__ __half g_yh [(size_t)NROWS * DIE];
__device__ float  g_o  [(size_t)NROWS * DD];
__device__ __half g_xh [(size_t)NROWS * DD];        // fp16 x
__device__ __half g_w1h[(size_t)2 * DIE * DD];
__device__ __half g_wfh[(size_t)DIE * DIE];
__device__ __half g_wbh[(size_t)DIE * DIE];
__device__ __half g_woh[(size_t)DD * DIE];

__device__ __forceinline__ float silu_f(float v) {
    return v / (1.f + __expf(-v));
}

__device__ __forceinline__ uint32_t smem_to_u32(const void* p) {
    uint32_t a;
    asm("{ .reg .u64 t; cvta.to.shared.u64 t, %1; cvt.u32.u64 %0, t; }" : "=r"(a) : "l"(p));
    return a;
}

__device__ __forceinline__ void mma_f16(float* c, const uint32_t* a,
                                        uint32_t b0, uint32_t b1) {
    asm volatile(
        "mma.sync.aligned.m16n8k16.row.col.f32.f16.f16.f32 "
        "{%0,%1,%2,%3}, {%4,%5,%6,%7}, {%8,%9}, {%0,%1,%2,%3};"
        : "+f"(c[0]), "+f"(c[1]), "+f"(c[2]), "+f"(c[3])
        : "r"(a[0]), "r"(a[1]), "r"(a[2]), "r"(a[3]), "r"(b0), "r"(b1));
}

__device__ __forceinline__ void ldsm4(uint32_t* r, uint32_t addr) {
    asm volatile("ldmatrix.sync.aligned.m8n8.x4.shared.b16 {%0,%1,%2,%3}, [%4];"
        : "=r"(r[0]), "=r"(r[1]), "=r"(r[2]), "=r"(r[3]) : "r"(addr));
}

#define CP16(dst, src) \
    asm volatile("cp.async.cg.shared.global [%0], [%1], 16;" :: "r"(dst), "l"(src))
#define CP_COMMIT() asm volatile("cp.async.commit_group;" ::: "memory")
#define CP_WAIT1()  asm volatile("cp.async.wait_group 1;" ::: "memory")

// ============ fp16 GEMM: C[M,N] = A[M,K] * B[N,K]^T, fp32 accumulate =========
// 128x128x64 CTA tile, 128 threads, 4 warps (2M x 2N), warp tile 64x64.
// 3-stage cp.async pipeline; stage = A 16KB + B 16KB (K-major, 128B rows of
// 64 halfs, 16B-group swizzle group' = kg ^ (row&7)). Fragments via native
// ldmatrix.x4 b16; mma m16n8k16 (a={r0..r3}, b={r0,r1}/{r2,r3}).
// EPI==0: C = acc            EPI==1: C = silu(acc + bias[n])
// OUTF==0: store __half      OUTF==1: store float
#define ST_STRIDE 32768u
template<int EPI, int OUTF>
__global__ void __launch_bounds__(128, 2)
gemm_f16(const __half* __restrict__ A, const __half* __restrict__ B,
         const float* __restrict__ bias, void* __restrict__ Cv,
         int M, int N, int K)
{
    extern __shared__ char smem[];
    const uint32_t al = smem_to_u32(smem);

    const int tid = threadIdx.x;
    const int wid = tid >> 5, l = tid & 31;
    const int wm = wid >> 1, wn = wid & 1;

    const size_t row0 = (size_t)blockIdx.y * 128;
    const size_t col0 = (size_t)blockIdx.x * 128;

    // ---- cp.async invariants: thread -> (row = tid>>3 + 16i, 16B-group = tid&7)
    const int ldr = tid >> 3;        // 0..15
    const int ldkg = tid & 7;
    const uint32_t sg = (uint32_t)(ldkg ^ (ldr & 7)) << 4;
    const __half* gA = A + (row0 + ldr) * (size_t)K + ldkg * 8;
    const __half* gB = B + (col0 + ldr) * (size_t)K + ldkg * 8;
    const uint32_t sA0 = al + ldr * 128 + sg;
    const uint32_t sB0 = al + 16384 + ldr * 128 + sg;

    // ---- fragment address invariants
    const uint32_t lr = l & 7, g01 = (l >> 3) & 1, g2 = (uint32_t)l >> 4;
    uint32_t aRow[4], bRow[4];
#pragma unroll
    for (int mi = 0; mi < 4; mi++)
        aRow[mi] = al + (uint32_t)(wm * 64 + mi * 16 + g01 * 8 + lr) * 128;
#pragma unroll
    for (int p = 0; p < 4; p++)
        bRow[p] = al + 16384 + (uint32_t)(wn * 64 + p * 16 + g2 * 8 + lr) * 128;

    float acc[4][8][4];
#pragma unroll
    for (int mi = 0; mi < 4; mi++)
#pragma unroll
        for (int j = 0; j < 8; j++)
#pragma unroll
            for (int t = 0; t < 4; t++) acc[mi][j][t] = 0.f;

    const int NC = K >> 6;     // 64 halfs per chunk

    // ---- prologue: chunks 0,1 into stages 0,1
#pragma unroll
    for (int s = 0; s < 2; s++) {
        const __half* pa = gA + s * 64;
        const __half* pb = gB + s * 64;
        uint32_t da = sA0 + s * ST_STRIDE;
        uint32_t db = sB0 + s * ST_STRIDE;
#pragma unroll
        for (int i = 0; i < 8; i++) {
            CP16(da + i * 2048, pa + (size_t)i * 16 * K);
            CP16(db + i * 2048, pb + (size_t)i * 16 * K);
        }
        CP_COMMIT();
    }

    for (int c = 0; c < NC; ++c) {
        CP_WAIT1();
        __syncthreads();
        if (c + 2 < NC) {
            const int st = (c + 2) % 3;
            const __half* pa = gA + (size_t)(c + 2) * 64;
            const __half* pb = gB + (size_t)(c + 2) * 64;
            uint32_t da = sA0 + st * ST_STRIDE;
            uint32_t db = sB0 + st * ST_STRIDE;
#pragma unroll
            for (int i = 0; i < 8; i++) {
                CP16(da + i * 2048, pa + (size_t)i * 16 * K);
                CP16(db + i * 2048, pb + (size_t)i * 16 * K);
            }
        }
        CP_COMMIT();

        const uint32_t stOff = (uint32_t)(c % 3) * ST_STRIDE;
#pragma unroll
        for (int s = 0; s < 4; s++) {          // 4 k16-steps per 64-K chunk
            const uint32_t aOff = stOff + ((((uint32_t)(2 * s) + g2) ^ lr) << 4);
            const uint32_t bOff = stOff + ((((uint32_t)(2 * s) + g01) ^ lr) << 4);
            uint32_t af[4][4], bf[4][4];
#pragma unroll
            for (int mi = 0; mi < 4; mi++) ldsm4(af[mi], aRow[mi] + aOff);
#pragma unroll
            for (int p = 0; p < 4; p++)  ldsm4(bf[p], bRow[p] + bOff);
#pragma unroll
            for (int mi = 0; mi < 4; mi++)
#pragma unroll
                for (int p = 0; p < 4; p++) {
                    mma_f16(acc[mi][2 * p],     af[mi], bf[p][0], bf[p][1]);
                    mma_f16(acc[mi][2 * p + 1], af[mi], bf[p][2], bf[p][3]);
                }
        }
    }

    // ---- epilogue
    const int gq = l >> 2, qq = l & 3;
#pragma unroll
    for (int mi = 0; mi < 4; mi++) {
        size_t r1 = row0 + wm * 64 + mi * 16 + gq;
#pragma unroll
        for (int nj = 0; nj < 8; nj++) {
            size_t cc = col0 + wn * 64 + nj * 8 + qq * 2;
            float v00 = acc[mi][nj][0], v01 = acc[mi][nj][1];
            float v10 = acc[mi][nj][2], v11 = acc[mi][nj][3];
            if (EPI == 1) {
                float2 bb = *(const float2*)(bias + cc);
                v00 = silu_f(v00 + bb.x); v01 = silu_f(v01 + bb.y);
                v10 = silu_f(v10 + bb.x); v11 = silu_f(v11 + bb.y);
            }
            if (OUTF == 1) {
                float* C = (float*)Cv;
                *(float2*)(C + r1 * N + cc)       = make_float2(v00, v01);
                *(float2*)(C + (r1 + 8) * N + cc) = make_float2(v10, v11);
            } else {
                __half* C = (__half*)Cv;
                *(__half2*)(C + r1 * N + cc)       = __floats2half2_rn(v00, v01);
                *(__half2*)(C + (r1 + 8) * N + cc) = __floats2half2_rn(v10, v11);
            }
        }
    }
}

// ---------------- fp32 -> fp16 convert (4 elems / thread) ---------------------
__global__ void to_half(const float* __restrict__ src, __half* __restrict__ dst,
                        long long n4)
{
    long long i = (long long)blockIdx.x * blockDim.x + threadIdx.x;
    if (i < n4) {
        float4 v = ((const float4*)src)[i];
        __half2* d2 = (__half2*)dst;
        d2[2 * i]     = __floats2half2_rn(v.x, v.y);
        d2[2 * i + 1] = __floats2half2_rn(v.z, v.w);
    }
}

// ---------------- fused depthwise causal (fwd) + anti-causal (bwd) conv ----------
// cf[m,c] = bf[c] + sum_k xp[m-6+k,c]*wf[c,k];  cb anti-causal with flipped wb.
__global__ void conv_dw(const __half* __restrict__ xz,
                        const float* __restrict__ wf, const float* __restrict__ bf,
                        const float* __restrict__ wb, const float* __restrict__ bb,
                        __half* __restrict__ cf, __half* __restrict__ cb)
{
    long long id = (long long)blockIdx.x * blockDim.x + threadIdx.x;
    int c = (int)(id & (DIE - 1));
    long long m = id >> 10;
    int t = (int)(m & (TD - 1));
    long long base = m * (2 * DIE) + c;

    float accf = bf[c];
    float accb = bb[c];
#pragma unroll
    for (int k = 0; k < 7; k++) {
        float w = wf[c * 7 + k];
        float v = (t - 6 + k >= 0) ? __half2float(xz[base + (long long)(k - 6) * (2 * DIE)]) : 0.f;
        accf = fmaf(v, w, accf);
    }
#pragma unroll
    for (int j = 0; j < 7; j++) {
        float w = wb[c * 7 + (6 - j)];
        float v = (t + 1 + j < TD) ? __half2float(xz[base + (long long)(j + 1) * (2 * DIE)]) : 0.f;
        accb = fmaf(v, w, accb);
    }
    cf[id] = __float2half_rn(accf);
    cb[id] = __float2half_rn(accb);
}

// ---------------- combine: shifts + diag + gate -------------------------------
__global__ void combine_k(const __half* __restrict__ xz,
                          const __half* __restrict__ pf, const __half* __restrict__ pb,
                          const float* __restrict__ diag, const float* __restrict__ gate,
                          __half* __restrict__ y)
{
    long long id = (long long)blockIdx.x * blockDim.x + threadIdx.x;
    int e = (int)(id & (DIE - 1));
    long long m = id >> 10;
    int t = (int)(m & (TD - 1));

    float yf = (t > 0)      ? __half2float(pf[id - DIE]) : 0.f;
    float yb = (t < TD - 1) ? __half2float(pb[id])       : 0.f;
    float xp = __half2float(xz[m * (2 * DIE) + e]);
    float z  = __half2float(xz[m * (2 * DIE) + DIE + e]);
    y[id] = __float2half_rn((yf + yb + xp * diag[e]) * silu_f(z) * gate[0]);
}

// ---------------- residual + LayerNorm(512) -----------------------------------
__device__ __forceinline__ float warp_sum(float v) {
#pragma unroll
    for (int o = 16; o > 0; o >>= 1) v += __shfl_down_sync(0xffffffffu, v, o);
    return v;
}

__global__ void ln_kernel(const float* __restrict__ x, const float* __restrict__ o,
                          const float* __restrict__ g, const float* __restrict__ b,
                          float* __restrict__ out)
{
    const int m = blockIdx.x;
    const int tid = threadIdx.x;
    const size_t base = (size_t)m * DD;

    float4 xv = ((const float4*)(x + base))[tid];
    float4 ov = ((const float4*)(o + base))[tid];
    float4 h = make_float4(xv.x + ov.x, xv.y + ov.y, xv.z + ov.z, xv.w + ov.w);

    float s  = h.x + h.y + h.z + h.w;
    float ss = h.x * h.x + h.y * h.y + h.z * h.z + h.w * h.w;

    __shared__ float sh[4], sh2[4];
    float ws  = warp_sum(s);
    float wss = warp_sum(ss);
    if ((tid & 31) == 0) { sh[tid >> 5] = ws; sh2[tid >> 5] = wss; }
    __syncthreads();
    if (tid < 32) {
        float a  = (tid < 4) ? sh[tid]  : 0.f;
        float a2 = (tid < 4) ? sh2[tid] : 0.f;
        a  = warp_sum(a);
        a2 = warp_sum(a2);
        if (tid == 0) { sh[0] = a; sh2[0] = a2; }
    }
    __syncthreads();

    float mu  = sh[0] * (1.f / DD);
    float var = sh2[0] * (1.f / DD) - mu * mu;
    float inv = rsqrtf(var + LN_EPS);

    float4 gv = ((const float4*)g)[tid];
    float4 bv = ((const float4*)b)[tid];
    float4 r;
    r.x = (h.x - mu) * inv * gv.x + bv.x;
    r.y = (h.y - mu) * inv * gv.y + bv.y;
    r.z = (h.z - mu) * inv * gv.z + bv.z;
    r.w = (h.w - mu) * inv * gv.w + bv.w;
    ((float4*)(out + base))[tid] = r;
}

// ---------------- launch ------------------------------------------------------
#define GEMM_SMEM (3 * 32768)   // 96 KB

extern "C" void kernel_launch(void* const* d_in, const int* in_sizes, int n_in,
                              void* d_out, int out_size)
{
    const float* x          = (const float*)d_in[0];
    const float* in_proj_w  = (const float*)d_in[1];
    const float* conv_fwd_w = (const float*)d_in[2];
    const float* conv_fwd_b = (const float*)d_in[3];
    const float* proj_fwd_w = (const float*)d_in[4];
    const float* proj_fwd_b = (const float*)d_in[5];
    const float* conv_bwd_w = (const float*)d_in[6];
    const float* conv_bwd_b = (const float*)d_in[7];
    const float* proj_bwd_w = (const float*)d_in[8];
    const float* proj_bwd_b = (const float*)d_in[9];
    const float* diag       = (const float*)d_in[10];
    const float* gate       = (const float*)d_in[11];
    const float* out_proj_w = (const float*)d_in[12];
    const float* ln_g       = (const float*)d_in[13];
    const float* ln_b       = (const float*)d_in[14];

    __half *xzh, *cfh, *cbh, *pfh, *pbh, *yh, *xh, *w1h, *wfh, *wbh, *woh;
    float *o;
    cudaGetSymbolAddress((void**)&xzh, g_xzh);
    cudaGetSymbolAddress((void**)&cfh, g_cfh);
    cudaGetSymbolAddress((void**)&cbh, g_cbh);
    cudaGetSymbolAddress((void**)&pfh, g_pfh);
    cudaGetSymbolAddress((void**)&pbh, g_pbh);
    cudaGetSymbolAddress((void**)&yh,  g_yh);
    cudaGetSymbolAddress((void**)&o,   g_o);
    cudaGetSymbolAddress((void**)&xh,  g_xh);
    cudaGetSymbolAddress((void**)&w1h, g_w1h);
    cudaGetSymbolAddress((void**)&wfh, g_wfh);
    cudaGetSymbolAddress((void**)&wbh, g_wbh);
    cudaGetSymbolAddress((void**)&woh, g_woh);

    cudaFuncSetAttribute(gemm_f16<0, 0>, cudaFuncAttributeMaxDynamicSharedMemorySize, GEMM_SMEM);
    cudaFuncSetAttribute(gemm_f16<1, 0>, cudaFuncAttributeMaxDynamicSharedMemorySize, GEMM_SMEM);
    cudaFuncSetAttribute(gemm_f16<0, 1>, cudaFuncAttributeMaxDynamicSharedMemorySize, GEMM_SMEM);

    // 0) fp16 conversion of x + all weights
    {
        long long n4;
        n4 = (long long)NROWS * DD / 4;
        to_half<<<(unsigned)((n4 + 255) / 256), 256>>>(x, xh, n4);
        n4 = (long long)2 * DIE * DD / 4;
        to_half<<<(unsigned)((n4 + 255) / 256), 256>>>(in_proj_w, w1h, n4);
        n4 = (long long)DIE * DIE / 4;
        to_half<<<(unsigned)((n4 + 255) / 256), 256>>>(proj_fwd_w, wfh, n4);
        to_half<<<(unsigned)((n4 + 255) / 256), 256>>>(proj_bwd_w, wbh, n4);
        n4 = (long long)DD * DIE / 4;
        to_half<<<(unsigned)((n4 + 255) / 256), 256>>>(out_proj_w, woh, n4);
    }

    // 1) xz = x @ in_proj_w^T          (32768 x 2048, K=512)
    gemm_f16<0, 0><<<dim3(2048 / 128, NROWS / 128), 128, GEMM_SMEM>>>(
        xh, w1h, nullptr, xzh, NROWS, 2048, DD);
    // 2) both depthwise convs
    conv_dw<<<(NROWS * DIE) / 256, 256>>>(xzh, conv_fwd_w, conv_fwd_b,
                                          conv_bwd_w, conv_bwd_b, cfh, cbh);
    // 3) pf = silu(cf @ wf^T + b)
    gemm_f16<1, 0><<<dim3(DIE / 128, NROWS / 128), 128, GEMM_SMEM>>>(
        cfh, wfh, proj_fwd_b, pfh, NROWS, DIE, DIE);
    // 4) pb = silu(cb @ wb^T + b)
    gemm_f16<1, 0><<<dim3(DIE / 128, NROWS / 128), 128, GEMM_SMEM>>>(
        cbh, wbh, proj_bwd_b, pbh, NROWS, DIE, DIE);
    // 5) y = (shift(pf) + mask(pb) + x_proj*diag) * silu(z) * gate
    combine_k<<<(NROWS * DIE) / 256, 256>>>(xzh, pfh, pbh, diag, gate, yh);
    // 6) o = y @ wo^T             (32768 x 512, K=1024)
    gemm_f16<0, 1><<<dim3(DD / 128, NROWS / 128), 128, GEMM_SMEM>>>(
        yh, woh, nullptr, o, NROWS, DD, DIE);
    // 7) out = LayerNorm(x + o)
    ln_kernel<<<NROWS, 128>>>(x, o, ln_g, ln_b, (float*)d_out);
}